// round 1
// baseline (speedup 1.0000x reference)
#include <cuda_runtime.h>
#include <cstdint>

#define B_ 1024
#define H_ 512
#define N_ 16384
#define M_ 64
#define EPSF 1e-6f

// ---- scratch (static device globals; no cudaMalloc allowed) ----
__device__ float g_mT[M_ * N_];        // m_t transposed [64][16384]
__device__ float g_mn[N_];             // ||m_t[n]||
__device__ float g_KT[M_ * B_];        // k_t transposed [64][1024]
__device__ float g_params[B_ * 8];     // per-b: beta, kn, g, gamma, s0, s1, s2, pad
__device__ float g_E[B_ * N_];         // exp(scores) [1024][16384] = 64 MB

// ======================================================================
// Kernel 1: transpose m_t -> g_mT and compute row norms g_mn
// grid 256 blocks x 256 threads, each block handles 64 memory rows
// ======================================================================
__global__ void __launch_bounds__(256) k_mprep(const float* __restrict__ m) {
    __shared__ float tile[64][65];
    int t = threadIdx.x;
    int n0 = blockIdx.x * 64;
    // load 64x64 tile coalesced (float4)
    #pragma unroll
    for (int it = 0; it < 4; ++it) {
        int f = t + it * 256;              // 1024 float4s
        int r = f >> 4;
        int c = (f & 15) << 2;
        float4 v = *(const float4*)&m[(n0 + r) * M_ + c];
        tile[r][c] = v.x; tile[r][c + 1] = v.y; tile[r][c + 2] = v.z; tile[r][c + 3] = v.w;
    }
    __syncthreads();
    // write transposed, coalesced over n
    #pragma unroll
    for (int it = 0; it < 16; ++it) {
        int f = t + it * 256;
        int r = f & 63;                    // n within tile
        int k = f >> 6;                    // feature
        g_mT[k * N_ + n0 + r] = tile[r][k];
    }
    // row norms
    if (t < 64) {
        float s = 0.f;
        #pragma unroll
        for (int k = 0; k < 64; ++k) { float v = tile[t][k]; s += v * v; }
        g_mn[n0 + t] = sqrtf(s);
    }
}

// ======================================================================
// Kernel 2: projections. grid 128 blocks (8 batch rows each) x 256 thr.
// 70 dot products of length 512 per batch row, warp-cooperative.
// W matrices (~140 KB) become L1-resident across the 8 rows.
// ======================================================================
__global__ void __launch_bounds__(256) k_proj(
    const float* __restrict__ h,
    const float* __restrict__ Wk, const float* __restrict__ bk,
    const float* __restrict__ Wb, const float* __restrict__ bbp,
    const float* __restrict__ Wg, const float* __restrict__ bgp,
    const float* __restrict__ Ws, const float* __restrict__ bsp,
    const float* __restrict__ Wm, const float* __restrict__ bmp) {
    __shared__ float hs[512];
    __shared__ float raw[70];
    __shared__ float sq[64];
    int t = threadIdx.x, lane = t & 31, wid = t >> 5;

    for (int bb = 0; bb < 8; ++bb) {
        int b = blockIdx.x * 8 + bb;
        hs[t]       = h[b * H_ + t];
        hs[t + 256] = h[b * H_ + 256 + t];
        __syncthreads();

        for (int j = wid; j < 70; j += 8) {
            const float* Wr; float bias;
            if (j < 64)       { Wr = Wk + j * H_;        bias = bk[j]; }
            else if (j == 64) { Wr = Wb;                 bias = bbp[0]; }
            else if (j == 65) { Wr = Wg;                 bias = bgp[0]; }
            else if (j == 66) { Wr = Wm;                 bias = bmp[0]; }
            else              { Wr = Ws + (j - 67) * H_; bias = bsp[j - 67]; }
            float s = 0.f;
            #pragma unroll 4
            for (int i = lane; i < H_; i += 32) s += Wr[i] * hs[i];
            #pragma unroll
            for (int o = 16; o; o >>= 1) s += __shfl_down_sync(0xffffffffu, s, o);
            if (lane == 0) raw[j] = s + bias;
        }
        __syncthreads();

        if (t < 64) {
            float kv = fminf(fmaxf(raw[t], 0.f), 1.f);   // clip(.,0,1)
            g_KT[t * B_ + b] = kv;
            sq[t] = kv * kv;
        }
        __syncthreads();

        if (wid == 0) {
            float v = sq[lane] + sq[lane + 32];
            #pragma unroll
            for (int o = 16; o; o >>= 1) v += __shfl_down_sync(0xffffffffu, v, o);
            if (lane == 0) {
                g_params[b * 8 + 0] = fmaxf(raw[64], 0.f);               // beta
                g_params[b * 8 + 1] = sqrtf(v);                          // ||k||
                g_params[b * 8 + 2] = fminf(fmaxf(raw[65], 0.f), 1.f);   // g
                g_params[b * 8 + 3] = 1.f + fmaxf(raw[66], 0.f);         // gamma
                float r0 = raw[67], r1 = raw[68], r2 = raw[69];
                float mx = fmaxf(r0, fmaxf(r1, r2));
                float e0 = __expf(r0 - mx), e1 = __expf(r1 - mx), e2 = __expf(r2 - mx);
                float is = 1.f / (e0 + e1 + e2);
                g_params[b * 8 + 4] = e0 * is;
                g_params[b * 8 + 5] = e1 * is;
                g_params[b * 8 + 6] = e2 * is;
            }
        }
        __syncthreads();
    }
}

// ======================================================================
// Kernel 3: GEMM  num[b,n] = sum_k KT[k][b] * mT[k][n]  (K=64)
// fused epilogue: E = exp(num * beta / (||k||*||m|| + eps))
// 128x128 tile / CTA, 256 threads, 8x8 per thread, packed f32x2 FFMA.
// ======================================================================
__device__ __forceinline__ void ffma2(unsigned long long& d,
                                      unsigned long long a,
                                      unsigned long long b) {
    asm("fma.rn.f32x2 %0, %1, %2, %0;" : "+l"(d) : "l"(a), "l"(b));
}
__device__ __forceinline__ unsigned long long pack2(float v) {
    unsigned long long r;
    asm("mov.b64 %0, {%1, %1};" : "=l"(r) : "f"(v));
    return r;
}
__device__ __forceinline__ float2 unpack2(unsigned long long v) {
    float2 r;
    asm("mov.b64 {%0, %1}, %2;" : "=f"(r.x), "=f"(r.y) : "l"(v));
    return r;
}

__global__ void __launch_bounds__(256) k_gemm() {
    extern __shared__ float sm[];
    float* As = sm;               // [64][128] k-major slice of KT
    float* Bs = sm + 64 * 128;    // [64][128] k-major slice of mT
    int t = threadIdx.x;
    int n0 = blockIdx.x * 128;
    int b0 = blockIdx.y * 128;

    #pragma unroll
    for (int it = 0; it < 8; ++it) {
        int f = t + it * 256;              // 2048 float4s per operand
        int row = f >> 5;
        int c = (f & 31) << 2;
        *(float4*)&As[row * 128 + c] = *(const float4*)&g_KT[row * B_ + b0 + c];
        *(float4*)&Bs[row * 128 + c] = *(const float4*)&g_mT[row * N_ + n0 + c];
    }
    __syncthreads();

    int tx = t & 15, ty = t >> 4;
    int bs_ = ty * 8, ns_ = tx * 8;

    unsigned long long c[8][4];
    #pragma unroll
    for (int i = 0; i < 8; ++i)
        #pragma unroll
        for (int j = 0; j < 4; ++j) c[i][j] = 0ull;

    #pragma unroll 8
    for (int k = 0; k < 64; ++k) {
        float4 a0 = *(float4*)&As[k * 128 + bs_];
        float4 a1 = *(float4*)&As[k * 128 + bs_ + 4];
        ulonglong2 bv0 = *(ulonglong2*)&Bs[k * 128 + ns_];      // 4 n-values as 2 packed pairs
        ulonglong2 bv1 = *(ulonglong2*)&Bs[k * 128 + ns_ + 4];
        unsigned long long aa[8];
        aa[0] = pack2(a0.x); aa[1] = pack2(a0.y); aa[2] = pack2(a0.z); aa[3] = pack2(a0.w);
        aa[4] = pack2(a1.x); aa[5] = pack2(a1.y); aa[6] = pack2(a1.z); aa[7] = pack2(a1.w);
        #pragma unroll
        for (int i = 0; i < 8; ++i) {
            ffma2(c[i][0], aa[i], bv0.x);
            ffma2(c[i][1], aa[i], bv0.y);
            ffma2(c[i][2], aa[i], bv1.x);
            ffma2(c[i][3], aa[i], bv1.y);
        }
    }

    // epilogue: scale by beta / (kn*mn + eps), exp, store
    float mnv[8];
    #pragma unroll
    for (int j = 0; j < 8; ++j) mnv[j] = g_mn[n0 + ns_ + j];

    #pragma unroll
    for (int i = 0; i < 8; ++i) {
        int b = b0 + bs_ + i;
        float beta = g_params[b * 8 + 0];
        float kn   = g_params[b * 8 + 1];
        float e[8];
        #pragma unroll
        for (int j = 0; j < 4; ++j) {
            float2 p = unpack2(c[i][j]);
            float n_lo = p.x, n_hi = p.y;
            e[2 * j]     = __expf(__fdividef(n_lo * beta, kn * mnv[2 * j] + EPSF));
            e[2 * j + 1] = __expf(__fdividef(n_hi * beta, kn * mnv[2 * j + 1] + EPSF));
        }
        float* dst = &g_E[b * N_ + n0 + ns_];
        *(float4*)dst       = make_float4(e[0], e[1], e[2], e[3]);
        *(float4*)(dst + 4) = make_float4(e[4], e[5], e[6], e[7]);
    }
}

// ======================================================================
// Kernel 4: per-row fused tail. grid = 1024 rows, 512 threads, 64 KB smem.
// softmax-normalize, gate, width-3 conv, pow, renormalize -> out
// ======================================================================
__device__ __forceinline__ float blockReduceSum(float v, float* red) {
    int lane = threadIdx.x & 31, wid = threadIdx.x >> 5;
    #pragma unroll
    for (int o = 16; o; o >>= 1) v += __shfl_down_sync(0xffffffffu, v, o);
    if (lane == 0) red[wid] = v;
    __syncthreads();
    if (wid == 0) {
        float x = (lane < 16) ? red[lane] : 0.f;
        #pragma unroll
        for (int o = 8; o; o >>= 1) x += __shfl_down_sync(0xffffffffu, x, o);
        if (lane == 0) red[16] = x;
    }
    __syncthreads();
    return red[16];
}

__global__ void __launch_bounds__(512) k_row(const float* __restrict__ w_tm1,
                                             float* __restrict__ out) {
    extern __shared__ float swg[];         // 16384 floats
    __shared__ float red[17];
    int t = threadIdx.x;
    int b = blockIdx.x;
    const float* Erow = &g_E[b * N_];
    const float* Wrow = &w_tm1[b * N_];
    float* Orow = &out[b * N_];

    // pass 1: load E row (keep in regs), softmax denominator
    float4 ev[8];
    float se = 0.f;
    #pragma unroll
    for (int i = 0; i < 8; ++i) {
        int p = i * 512 + t;
        ev[i] = *(const float4*)&Erow[p * 4];
        se += ev[i].x + ev[i].y + ev[i].z + ev[i].w;
    }
    float inv_e = 1.0f / blockReduceSum(se, red);

    float g     = g_params[b * 8 + 2];
    float gamma = g_params[b * 8 + 3];
    float s0    = g_params[b * 8 + 4];
    float s1    = g_params[b * 8 + 5];
    float s2    = g_params[b * 8 + 6];
    float gi = 1.f - g;

    // pass 2: gated interpolation -> smem
    #pragma unroll
    for (int i = 0; i < 8; ++i) {
        int p = i * 512 + t;
        float4 wt = *(const float4*)&Wrow[p * 4];
        float4 wg;
        wg.x = g * ev[i].x * inv_e + gi * wt.x;
        wg.y = g * ev[i].y * inv_e + gi * wt.y;
        wg.z = g * ev[i].z * inv_e + gi * wt.z;
        wg.w = g * ev[i].w * inv_e + gi * wt.w;
        *(float4*)&swg[p * 4] = wg;
    }
    __syncthreads();

    // pass 3: shift conv + sharpening
    float4 wv[8];
    float sw = 0.f;
    #pragma unroll
    for (int i = 0; i < 8; ++i) {
        int w0 = (i * 512 + t) * 4;
        float xm = (w0 == 0) ? 0.f : swg[w0 - 1];
        float4 x = *(float4*)&swg[w0];
        float xp = (w0 + 4 == N_) ? 0.f : swg[w0 + 4];
        float t0 = s0 * xm  + s1 * x.x + s2 * x.y;
        float t1 = s0 * x.x + s1 * x.y + s2 * x.z;
        float t2 = s0 * x.y + s1 * x.z + s2 * x.w;
        float t3 = s0 * x.z + s1 * x.w + s2 * xp;
        wv[i].x = __powf(t0 + 1e-6f, gamma);
        wv[i].y = __powf(t1 + 1e-6f, gamma);
        wv[i].z = __powf(t2 + 1e-6f, gamma);
        wv[i].w = __powf(t3 + 1e-6f, gamma);
        sw += wv[i].x + wv[i].y + wv[i].z + wv[i].w;
    }
    float inv_w = 1.0f / blockReduceSum(sw, red);

    // pass 4: normalized output
    #pragma unroll
    for (int i = 0; i < 8; ++i) {
        int w0 = (i * 512 + t) * 4;
        float4 o;
        o.x = wv[i].x * inv_w; o.y = wv[i].y * inv_w;
        o.z = wv[i].z * inv_w; o.w = wv[i].w * inv_w;
        *(float4*)&Orow[w0] = o;
    }
}

// ======================================================================
extern "C" void kernel_launch(void* const* d_in, const int* in_sizes, int n_in,
                              void* d_out, int out_size) {
    const float* h_t   = (const float*)d_in[0];
    const float* w_tm1 = (const float*)d_in[1];
    const float* m_t   = (const float*)d_in[2];
    const float* Wk    = (const float*)d_in[3];
    const float* bk    = (const float*)d_in[4];
    const float* Wb    = (const float*)d_in[5];
    const float* bb    = (const float*)d_in[6];
    const float* Wg    = (const float*)d_in[7];
    const float* bg    = (const float*)d_in[8];
    const float* Ws    = (const float*)d_in[9];
    const float* bs    = (const float*)d_in[10];
    const float* Wm    = (const float*)d_in[11];
    const float* bm    = (const float*)d_in[12];
    float* out = (float*)d_out;

    cudaFuncSetAttribute(k_gemm, cudaFuncAttributeMaxDynamicSharedMemorySize, 65536);
    cudaFuncSetAttribute(k_row,  cudaFuncAttributeMaxDynamicSharedMemorySize, 65536);

    k_mprep<<<N_ / 64, 256>>>(m_t);
    k_proj<<<B_ / 8, 256>>>(h_t, Wk, bk, Wb, bb, Wg, bg, Ws, bs, Wm, bm);
    k_gemm<<<dim3(N_ / 128, B_ / 128), 256, 65536>>>();
    k_row<<<B_, 512, 65536>>>(w_tm1, out);
}

// round 3
// speedup vs baseline: 1.0943x; 1.0943x over previous
#include <cuda_runtime.h>
#include <cuda_bf16.h>
#include <cstdint>

#define B_ 1024
#define H_ 512
#define N_ 16384
#define M_ 64

// ---------------- scratch (static device globals) ----------------
__device__ __nv_bfloat16 g_mhi[N_ * M_];   // bf16 hi of m_t [N][64]
__device__ __nv_bfloat16 g_mlo[N_ * M_];   // bf16 lo of m_t
__device__ float g_inv_mn[N_];             // 1/||m_t[n]||
__device__ __nv_bfloat16 g_khi[B_ * M_];   // bf16 hi of k_t [B][64]
__device__ __nv_bfloat16 g_klo[B_ * M_];
__device__ float g_sb[B_];                 // beta / ||k||
__device__ float g_params[B_ * 8];         // g, gamma, s0,s1,s2
__device__ float g_E[B_ * N_];             // exp(scores) fp32 (64 MB)

__device__ __forceinline__ uint32_t smem_u32(const void* p) {
    uint32_t a;
    asm("{ .reg .u64 t; cvta.to.shared.u64 t, %1; cvt.u32.u64 %0, t; }" : "=r"(a) : "l"(p));
    return a;
}
__device__ __forceinline__ void ldsm_x4(uint32_t& r0, uint32_t& r1, uint32_t& r2, uint32_t& r3,
                                        uint32_t addr) {
    asm volatile("ldmatrix.sync.aligned.m8n8.x4.shared.b16 {%0,%1,%2,%3}, [%4];"
                 : "=r"(r0), "=r"(r1), "=r"(r2), "=r"(r3) : "r"(addr));
}
__device__ __forceinline__ void mma16816(float* c, uint32_t a0, uint32_t a1, uint32_t a2,
                                         uint32_t a3, uint32_t b0, uint32_t b1) {
    asm volatile(
        "mma.sync.aligned.m16n8k16.row.col.f32.bf16.bf16.f32 "
        "{%0,%1,%2,%3}, {%4,%5,%6,%7}, {%8,%9}, {%0,%1,%2,%3};"
        : "+f"(c[0]), "+f"(c[1]), "+f"(c[2]), "+f"(c[3])
        : "r"(a0), "r"(a1), "r"(a2), "r"(a3), "r"(b0), "r"(b1));
}

// ======================================================================
// Kernel 1 (fused): blocks [0,256): m prep  |  blocks [256,384): proj
// ======================================================================
__global__ void __launch_bounds__(256) k_prep(
    const float* __restrict__ m,
    const float* __restrict__ h,
    const float* __restrict__ Wk, const float* __restrict__ bk,
    const float* __restrict__ Wb, const float* __restrict__ bbp,
    const float* __restrict__ Wg, const float* __restrict__ bgp,
    const float* __restrict__ Ws, const float* __restrict__ bsp,
    const float* __restrict__ Wm, const float* __restrict__ bmp) {
    int t = threadIdx.x;
    if (blockIdx.x < 256) {
        // ---- m prep: bf16 hi/lo split + 1/row-norm; 64 rows / block ----
        int row = blockIdx.x * 64 + (t >> 2);
        int part = t & 3;
        const float4* src = (const float4*)(m + row * M_ + part * 16);
        float v[16];
        #pragma unroll
        for (int i = 0; i < 4; ++i) {
            float4 f = src[i];
            v[4 * i] = f.x; v[4 * i + 1] = f.y; v[4 * i + 2] = f.z; v[4 * i + 3] = f.w;
        }
        float s = 0.f;
        unsigned int ph[8], pl[8];
        #pragma unroll
        for (int i = 0; i < 8; ++i) {
            float a = v[2 * i], b = v[2 * i + 1];
            s += a * a + b * b;
            __nv_bfloat16 ha = __float2bfloat16(a), hb = __float2bfloat16(b);
            __nv_bfloat16 la = __float2bfloat16(a - __bfloat162float(ha));
            __nv_bfloat16 lb = __float2bfloat16(b - __bfloat162float(hb));
            ph[i] = (unsigned int)__bfloat16_as_ushort(ha) | ((unsigned int)__bfloat16_as_ushort(hb) << 16);
            pl[i] = (unsigned int)__bfloat16_as_ushort(la) | ((unsigned int)__bfloat16_as_ushort(lb) << 16);
        }
        uint4* dh = (uint4*)(g_mhi + row * M_ + part * 16);
        uint4* dl = (uint4*)(g_mlo + row * M_ + part * 16);
        dh[0] = make_uint4(ph[0], ph[1], ph[2], ph[3]);
        dh[1] = make_uint4(ph[4], ph[5], ph[6], ph[7]);
        dl[0] = make_uint4(pl[0], pl[1], pl[2], pl[3]);
        dl[1] = make_uint4(pl[4], pl[5], pl[6], pl[7]);
        s += __shfl_down_sync(0xffffffffu, s, 2);
        s += __shfl_down_sync(0xffffffffu, s, 1);
        if (part == 0) g_inv_mn[row] = rsqrtf(fmaxf(s, 1e-24f));
        return;
    }
    // ---- projections: 70 dots of 512 per batch row, 8 rows / block ----
    __shared__ float hs[512];
    __shared__ float raw[70];
    __shared__ float sq[64];
    int lane = t & 31, wid = t >> 5;
    for (int bb = 0; bb < 8; ++bb) {
        int b = (blockIdx.x - 256) * 8 + bb;
        hs[t]       = h[b * H_ + t];
        hs[t + 256] = h[b * H_ + 256 + t];
        __syncthreads();

        for (int j = wid; j < 70; j += 8) {
            const float* Wr; float bias;
            if (j < 64)       { Wr = Wk + j * H_;        bias = bk[j]; }
            else if (j == 64) { Wr = Wb;                 bias = bbp[0]; }
            else if (j == 65) { Wr = Wg;                 bias = bgp[0]; }
            else if (j == 66) { Wr = Wm;                 bias = bmp[0]; }
            else              { Wr = Ws + (j - 67) * H_; bias = bsp[j - 67]; }
            float s = 0.f;
            #pragma unroll 4
            for (int i = lane; i < H_; i += 32) s += Wr[i] * hs[i];
            #pragma unroll
            for (int o = 16; o; o >>= 1) s += __shfl_down_sync(0xffffffffu, s, o);
            if (lane == 0) raw[j] = s + bias;
        }
        __syncthreads();

        if (t < 64) {
            float kv = fminf(fmaxf(raw[t], 0.f), 1.f);
            __nv_bfloat16 hv = __float2bfloat16(kv);
            __nv_bfloat16 lv = __float2bfloat16(kv - __bfloat162float(hv));
            g_khi[b * M_ + t] = hv;
            g_klo[b * M_ + t] = lv;
            sq[t] = kv * kv;
        }
        __syncthreads();

        if (wid == 0) {
            float v = sq[lane] + sq[lane + 32];
            #pragma unroll
            for (int o = 16; o; o >>= 1) v += __shfl_down_sync(0xffffffffu, v, o);
            if (lane == 0) {
                float beta = fmaxf(raw[64], 0.f);
                float kn = sqrtf(v);
                g_sb[b] = beta * kn / (kn * kn + 1e-12f);               // beta/||k||
                g_params[b * 8 + 2] = fminf(fmaxf(raw[65], 0.f), 1.f);  // g
                g_params[b * 8 + 3] = 1.f + fmaxf(raw[66], 0.f);        // gamma
                float r0 = raw[67], r1 = raw[68], r2 = raw[69];
                float mx = fmaxf(r0, fmaxf(r1, r2));
                float e0 = __expf(r0 - mx), e1 = __expf(r1 - mx), e2 = __expf(r2 - mx);
                float is = 1.f / (e0 + e1 + e2);
                g_params[b * 8 + 4] = e0 * is;
                g_params[b * 8 + 5] = e1 * is;
                g_params[b * 8 + 6] = e2 * is;
            }
        }
        __syncthreads();
    }
}

// ======================================================================
// Kernel 2: HMMA bf16 3-split GEMM. CTA tile 64(b) x 128(n), K=64.
// D = Ahi*Bhi + Ahi*Blo + Alo*Bhi. Epilogue: E = exp(D*sb[b]*inv_mn[n]).
// smem rows padded to 144B for conflict-free ldmatrix.
// ======================================================================
#define RSTRIDE 144          // bytes per 64-bf16 row in smem
#define OFF_A_HI 0
#define OFF_A_LO (64 * RSTRIDE)
#define OFF_B_HI (2 * 64 * RSTRIDE)
#define OFF_B_LO (OFF_B_HI + 128 * RSTRIDE)
#define OFF_INV  (OFF_B_LO + 128 * RSTRIDE)          // 128 floats
#define OFF_SBS  (OFF_INV + 512)                     // 64 floats
#define SMEM_GEMM (OFF_SBS + 256)

__global__ void __launch_bounds__(128) k_gemm_hmma() {
    extern __shared__ char sm[];
    uint32_t sbase = smem_u32(sm);
    int t = threadIdx.x;
    int lane = t & 31, wid = t >> 5;
    int n0 = blockIdx.x * 128;
    int b0 = blockIdx.y * 64;

    // stage operand tiles (rows of 64 bf16 = 8 x 16B chunks, padded stride)
    {
        const uint4* sa_hi = (const uint4*)(g_khi + (size_t)b0 * M_);
        const uint4* sa_lo = (const uint4*)(g_klo + (size_t)b0 * M_);
        #pragma unroll
        for (int it = 0; it < 4; ++it) {
            int idx = t + it * 128;                    // 512 chunks (64 rows)
            int r = idx >> 3, c = idx & 7;
            *(uint4*)(sm + OFF_A_HI + r * RSTRIDE + c * 16) = sa_hi[idx];
            *(uint4*)(sm + OFF_A_LO + r * RSTRIDE + c * 16) = sa_lo[idx];
        }
        const uint4* sb_hi = (const uint4*)(g_mhi + (size_t)n0 * M_);
        const uint4* sb_lo = (const uint4*)(g_mlo + (size_t)n0 * M_);
        #pragma unroll
        for (int it = 0; it < 8; ++it) {
            int idx = t + it * 128;                    // 1024 chunks (128 rows)
            int r = idx >> 3, c = idx & 7;
            *(uint4*)(sm + OFF_B_HI + r * RSTRIDE + c * 16) = sb_hi[idx];
            *(uint4*)(sm + OFF_B_LO + r * RSTRIDE + c * 16) = sb_lo[idx];
        }
        if (t < 64) {
            ((float*)(sm + OFF_INV))[t]      = g_inv_mn[n0 + t];
            ((float*)(sm + OFF_INV))[t + 64] = g_inv_mn[n0 + 64 + t];
            ((float*)(sm + OFF_SBS))[t]      = g_sb[b0 + t];
        }
    }
    __syncthreads();

    int wm = (wid >> 1) * 32;       // warp row base in CTA tile (b)
    int wn = (wid & 1) * 64;        // warp col base (n)
    int ltile = lane >> 3, lr = lane & 7;

    float acc[2][8][4];
    #pragma unroll
    for (int mi = 0; mi < 2; ++mi)
        #pragma unroll
        for (int nb = 0; nb < 8; ++nb)
            #pragma unroll
            for (int q = 0; q < 4; ++q) acc[mi][nb][q] = 0.f;

    #pragma unroll
    for (int pass = 0; pass < 3; ++pass) {
        uint32_t aOff = (pass == 2) ? OFF_A_LO : OFF_A_HI;
        uint32_t bOff = (pass == 1) ? OFF_B_LO : OFF_B_HI;
        #pragma unroll
        for (int ks = 0; ks < 4; ++ks) {
            // A fragments: mi in {0,1}, tiles (m0,k0),(m8,k0),(m0,k8),(m8,k8)
            uint32_t a[2][4];
            #pragma unroll
            for (int mi = 0; mi < 2; ++mi) {
                int rowA = wm + mi * 16 + (ltile & 1) * 8 + lr;
                int col16 = ks * 2 + (ltile >> 1);
                ldsm_x4(a[mi][0], a[mi][1], a[mi][2], a[mi][3],
                        sbase + aOff + rowA * RSTRIDE + col16 * 16);
            }
            // B fragments: np n16-groups, tiles (n0,k0),(n0,k8),(n8,k0),(n8,k8)
            uint32_t bfr[8][2];
            #pragma unroll
            for (int np = 0; np < 4; ++np) {
                int rowB = wn + np * 16 + (ltile >> 1) * 8 + lr;
                int col16 = ks * 2 + (ltile & 1);
                ldsm_x4(bfr[2 * np][0], bfr[2 * np][1], bfr[2 * np + 1][0], bfr[2 * np + 1][1],
                        sbase + bOff + rowB * RSTRIDE + col16 * 16);
            }
            #pragma unroll
            for (int mi = 0; mi < 2; ++mi)
                #pragma unroll
                for (int nb = 0; nb < 8; ++nb)
                    mma16816(acc[mi][nb], a[mi][0], a[mi][1], a[mi][2], a[mi][3],
                             bfr[nb][0], bfr[nb][1]);
        }
    }

    // epilogue: scale, exp, store
    const float* inv_s = (const float*)(sm + OFF_INV);
    const float* sb_s  = (const float*)(sm + OFF_SBS);
    int r0 = lane >> 2, c0 = (lane & 3) * 2;
    #pragma unroll
    for (int mi = 0; mi < 2; ++mi) {
        int bl0 = wm + mi * 16 + r0;
        float s0 = sb_s[bl0], s1 = sb_s[bl0 + 8];
        float* d0 = &g_E[(size_t)(b0 + bl0) * N_ + n0];
        float* d1 = &g_E[(size_t)(b0 + bl0 + 8) * N_ + n0];
        #pragma unroll
        for (int nb = 0; nb < 8; ++nb) {
            int nl = wn + nb * 8 + c0;
            float i0 = inv_s[nl], i1 = inv_s[nl + 1];
            float2 e0, e1;
            e0.x = __expf(acc[mi][nb][0] * s0 * i0);
            e0.y = __expf(acc[mi][nb][1] * s0 * i1);
            e1.x = __expf(acc[mi][nb][2] * s1 * i0);
            e1.y = __expf(acc[mi][nb][3] * s1 * i1);
            *(float2*)(d0 + nl) = e0;
            *(float2*)(d1 + nl) = e1;
        }
    }
}

// ======================================================================
// Kernel 3: per-row fused tail (streaming, low-register).
// ======================================================================
__device__ __forceinline__ float blockReduceSum(float v, float* red) {
    int lane = threadIdx.x & 31, wid = threadIdx.x >> 5;
    #pragma unroll
    for (int o = 16; o; o >>= 1) v += __shfl_down_sync(0xffffffffu, v, o);
    if (lane == 0) red[wid] = v;
    __syncthreads();
    if (wid == 0) {
        float x = (lane < 16) ? red[lane] : 0.f;
        #pragma unroll
        for (int o = 8; o; o >>= 1) x += __shfl_down_sync(0xffffffffu, x, o);
        if (lane == 0) red[16] = x;
    }
    __syncthreads();
    return red[16];
}

__global__ void __launch_bounds__(512, 3) k_row(const float* __restrict__ w_tm1,
                                                float* __restrict__ out) {
    extern __shared__ float swg[];          // 16384 floats
    __shared__ float red[17];
    __shared__ float bnd[8];
    int t = threadIdx.x;
    int b = blockIdx.x;
    const float4* Erow = (const float4*)&g_E[(size_t)b * N_];
    const float4* Wrow = (const float4*)&w_tm1[(size_t)b * N_];
    float4* Orow = (float4*)&out[(size_t)b * N_];

    // pass A: E -> smem, softmax denominator
    float se = 0.f;
    #pragma unroll
    for (int i = 0; i < 8; ++i) {
        int p = i * 512 + t;
        float4 e = Erow[p];
        *(float4*)&swg[p * 4] = e;
        se += e.x + e.y + e.z + e.w;
    }
    float inv_e = 1.0f / blockReduceSum(se, red);

    float g     = g_params[b * 8 + 2];
    float gamma = g_params[b * 8 + 3];
    float s0    = g_params[b * 8 + 4];
    float s1    = g_params[b * 8 + 5];
    float s2    = g_params[b * 8 + 6];
    float gs = g * inv_e, gi = 1.f - g;

    // pass A2: gated interpolation in place (own chunks only)
    #pragma unroll
    for (int i = 0; i < 8; ++i) {
        int p = i * 512 + t;
        float4 e = *(float4*)&swg[p * 4];
        float4 wt = Wrow[p];
        float4 wg;
        wg.x = gs * e.x + gi * wt.x;
        wg.y = gs * e.y + gi * wt.y;
        wg.z = gs * e.z + gi * wt.z;
        wg.w = gs * e.w + gi * wt.w;
        *(float4*)&swg[p * 4] = wg;
    }
    __syncthreads();
    if (t < 8) bnd[t] = (t == 0) ? 0.f : swg[t * 2048 - 1];
    __syncthreads();

    // pass B: shift conv + sharpening, in place (1 bar per chunk)
    float sw = 0.f;
    #pragma unroll
    for (int i = 0; i < 8; ++i) {
        int w0 = (i * 512 + t) * 4;
        float xm = (t == 0) ? bnd[i] : swg[w0 - 1];
        float4 x = *(float4*)&swg[w0];
        float xp = (w0 + 4 == N_) ? 0.f : swg[w0 + 4];
        float t0 = s0 * xm  + s1 * x.x + s2 * x.y;
        float t1 = s0 * x.x + s1 * x.y + s2 * x.z;
        float t2 = s0 * x.y + s1 * x.z + s2 * x.w;
        float t3 = s0 * x.z + s1 * x.w + s2 * xp;
        float p0 = __powf(t0 + 1e-6f, gamma);
        float p1 = __powf(t1 + 1e-6f, gamma);
        float p2 = __powf(t2 + 1e-6f, gamma);
        float p3 = __powf(t3 + 1e-6f, gamma);
        __syncthreads();
        *(float4*)&swg[w0] = make_float4(p0, p1, p2, p3);
        sw += p0 + p1 + p2 + p3;
    }
    float inv_w = 1.0f / blockReduceSum(sw, red);

    // pass C: normalize and store
    #pragma unroll
    for (int i = 0; i < 8; ++i) {
        int p = i * 512 + t;
        float4 x = *(float4*)&swg[p * 4];
        Orow[p] = make_float4(x.x * inv_w, x.y * inv_w, x.z * inv_w, x.w * inv_w);
    }
}

// ======================================================================
extern "C" void kernel_launch(void* const* d_in, const int* in_sizes, int n_in,
                              void* d_out, int out_size) {
    const float* h_t   = (const float*)d_in[0];
    const float* w_tm1 = (const float*)d_in[1];
    const float* m_t   = (const float*)d_in[2];
    const float* Wk    = (const float*)d_in[3];
    const float* bk    = (const float*)d_in[4];
    const float* Wb    = (const float*)d_in[5];
    const float* bb    = (const float*)d_in[6];
    const float* Wg    = (const float*)d_in[7];
    const float* bg    = (const float*)d_in[8];
    const float* Ws    = (const float*)d_in[9];
    const float* bs    = (const float*)d_in[10];
    const float* Wm    = (const float*)d_in[11];
    const float* bm    = (const float*)d_in[12];
    float* out = (float*)d_out;

    cudaFuncSetAttribute(k_gemm_hmma, cudaFuncAttributeMaxDynamicSharedMemorySize, SMEM_GEMM);
    cudaFuncSetAttribute(k_row,       cudaFuncAttributeMaxDynamicSharedMemorySize, 65536);

    k_prep<<<384, 256>>>(m_t, h_t, Wk, bk, Wb, bb, Wg, bg, Ws, bs, Wm, bm);
    k_gemm_hmma<<<dim3(N_ / 128, B_ / 64), 128, SMEM_GEMM>>>();
    k_row<<<B_, 512, 65536>>>(w_tm1, out);
}

// round 5
// speedup vs baseline: 1.5362x; 1.4038x over previous
#include <cuda_runtime.h>
#include <cuda_bf16.h>
#include <cstdint>

#define B_ 1024
#define H_ 512
#define N_ 16384
#define M_ 64

// ---------------- scratch (static device globals) ----------------
__device__ __nv_bfloat16 g_mhi[N_ * M_];   // bf16 hi of m_t [N][64]
__device__ __nv_bfloat16 g_mlo[N_ * M_];   // bf16 lo of m_t
__device__ float g_inv_mn[N_];             // 1/||m_t[n]||
__device__ __nv_bfloat16 g_khi[B_ * M_];   // bf16 hi of k_t [B][64]
__device__ __nv_bfloat16 g_klo[B_ * M_];
__device__ float g_sb[B_];                 // beta / ||k||
__device__ float g_params[B_ * 8];         // g, gamma, s0,s1,s2
__device__ float g_E[B_ * N_];             // exp(scores) fp32 (64 MB)

__device__ __forceinline__ uint32_t smem_u32(const void* p) {
    uint32_t a;
    asm("{ .reg .u64 t; cvta.to.shared.u64 t, %1; cvt.u32.u64 %0, t; }" : "=r"(a) : "l"(p));
    return a;
}
__device__ __forceinline__ void ldsm_x4(uint32_t& r0, uint32_t& r1, uint32_t& r2, uint32_t& r3,
                                        uint32_t addr) {
    asm volatile("ldmatrix.sync.aligned.m8n8.x4.shared.b16 {%0,%1,%2,%3}, [%4];"
                 : "=r"(r0), "=r"(r1), "=r"(r2), "=r"(r3) : "r"(addr));
}
__device__ __forceinline__ void mma16816(float* c, uint32_t a0, uint32_t a1, uint32_t a2,
                                         uint32_t a3, uint32_t b0, uint32_t b1) {
    asm volatile(
        "mma.sync.aligned.m16n8k16.row.col.f32.bf16.bf16.f32 "
        "{%0,%1,%2,%3}, {%4,%5,%6,%7}, {%8,%9}, {%0,%1,%2,%3};"
        : "+f"(c[0]), "+f"(c[1]), "+f"(c[2]), "+f"(c[3])
        : "r"(a0), "r"(a1), "r"(a2), "r"(a3), "r"(b0), "r"(b1));
}

// ======================================================================
// Kernel 1 (fused): blocks [0,256): m prep  |  blocks [256,512): proj
// proj: 4 batch rows / CTA, 8 warps; W rows loaded once, reused 4x.
// ======================================================================
__global__ void __launch_bounds__(256) k_prep(
    const float* __restrict__ m,
    const float* __restrict__ h,
    const float* __restrict__ Wk, const float* __restrict__ bk,
    const float* __restrict__ Wb, const float* __restrict__ bbp,
    const float* __restrict__ Wg, const float* __restrict__ bgp,
    const float* __restrict__ Ws, const float* __restrict__ bsp,
    const float* __restrict__ Wm, const float* __restrict__ bmp) {
    int t = threadIdx.x;
    if (blockIdx.x < 256) {
        // ---- m prep: bf16 hi/lo split + 1/row-norm; 64 rows / block ----
        int row = blockIdx.x * 64 + (t >> 2);
        int part = t & 3;
        const float4* src = (const float4*)(m + row * M_ + part * 16);
        float v[16];
        #pragma unroll
        for (int i = 0; i < 4; ++i) {
            float4 f = src[i];
            v[4 * i] = f.x; v[4 * i + 1] = f.y; v[4 * i + 2] = f.z; v[4 * i + 3] = f.w;
        }
        float s = 0.f;
        unsigned int ph[8], pl[8];
        #pragma unroll
        for (int i = 0; i < 8; ++i) {
            float a = v[2 * i], b = v[2 * i + 1];
            s += a * a + b * b;
            __nv_bfloat16 ha = __float2bfloat16(a), hb = __float2bfloat16(b);
            __nv_bfloat16 la = __float2bfloat16(a - __bfloat162float(ha));
            __nv_bfloat16 lb = __float2bfloat16(b - __bfloat162float(hb));
            ph[i] = (unsigned int)__bfloat16_as_ushort(ha) | ((unsigned int)__bfloat16_as_ushort(hb) << 16);
            pl[i] = (unsigned int)__bfloat16_as_ushort(la) | ((unsigned int)__bfloat16_as_ushort(lb) << 16);
        }
        uint4* dh = (uint4*)(g_mhi + row * M_ + part * 16);
        uint4* dl = (uint4*)(g_mlo + row * M_ + part * 16);
        dh[0] = make_uint4(ph[0], ph[1], ph[2], ph[3]);
        dh[1] = make_uint4(ph[4], ph[5], ph[6], ph[7]);
        dl[0] = make_uint4(pl[0], pl[1], pl[2], pl[3]);
        dl[1] = make_uint4(pl[4], pl[5], pl[6], pl[7]);
        s += __shfl_down_sync(0xffffffffu, s, 2);
        s += __shfl_down_sync(0xffffffffu, s, 1);
        if (part == 0) g_inv_mn[row] = rsqrtf(fmaxf(s, 1e-24f));
        return;
    }
    // ---- projections: 4 batch rows per CTA, W reused across rows ----
    __shared__ float hs[4][512];
    __shared__ float raw[4][72];
    __shared__ float sq[4][64];
    int lane = t & 31, wid = t >> 5;
    int b0 = (blockIdx.x - 256) * 4;

    // load 4 h rows (512 float4s total)
    #pragma unroll
    for (int it = 0; it < 2; ++it) {
        int idx = t + it * 256;                  // 0..511
        int r = idx >> 7, c = (idx & 127) * 4;
        *(float4*)&hs[r][c] = *(const float4*)&h[(b0 + r) * H_ + c];
    }
    __syncthreads();

    for (int j = wid; j < 70; j += 8) {
        const float* Wr; float bias;
        if (j < 64)       { Wr = Wk + j * H_;        bias = bk[j]; }
        else if (j == 64) { Wr = Wb;                 bias = bbp[0]; }
        else if (j == 65) { Wr = Wg;                 bias = bgp[0]; }
        else if (j == 66) { Wr = Wm;                 bias = bmp[0]; }
        else              { Wr = Ws + (j - 67) * H_; bias = bsp[j - 67]; }
        float a0 = 0.f, a1 = 0.f, a2 = 0.f, a3 = 0.f;
        #pragma unroll 4
        for (int i = lane; i < H_; i += 32) {
            float w = Wr[i];
            a0 += w * hs[0][i];
            a1 += w * hs[1][i];
            a2 += w * hs[2][i];
            a3 += w * hs[3][i];
        }
        #pragma unroll
        for (int o = 16; o; o >>= 1) {
            a0 += __shfl_down_sync(0xffffffffu, a0, o);
            a1 += __shfl_down_sync(0xffffffffu, a1, o);
            a2 += __shfl_down_sync(0xffffffffu, a2, o);
            a3 += __shfl_down_sync(0xffffffffu, a3, o);
        }
        if (lane == 0) {
            raw[0][j] = a0 + bias;
            raw[1][j] = a1 + bias;
            raw[2][j] = a2 + bias;
            raw[3][j] = a3 + bias;
        }
    }
    __syncthreads();

    // k store + squares: 256 threads = 4 rows x 64 elems
    {
        int bb = t >> 6, idx = t & 63;
        int b = b0 + bb;
        float kv = fminf(fmaxf(raw[bb][idx], 0.f), 1.f);
        __nv_bfloat16 hv = __float2bfloat16(kv);
        __nv_bfloat16 lv = __float2bfloat16(kv - __bfloat162float(hv));
        g_khi[b * M_ + idx] = hv;
        g_klo[b * M_ + idx] = lv;
        sq[bb][idx] = kv * kv;
    }
    __syncthreads();

    if (wid < 4) {
        int bb = wid, b = b0 + bb;
        float v = sq[bb][lane] + sq[bb][lane + 32];
        #pragma unroll
        for (int o = 16; o; o >>= 1) v += __shfl_down_sync(0xffffffffu, v, o);
        if (lane == 0) {
            float beta = fmaxf(raw[bb][64], 0.f);
            float kn = sqrtf(v);
            g_sb[b] = beta * kn / (kn * kn + 1e-12f);                 // beta/||k||
            g_params[b * 8 + 2] = fminf(fmaxf(raw[bb][65], 0.f), 1.f);
            g_params[b * 8 + 3] = 1.f + fmaxf(raw[bb][66], 0.f);
            float r0 = raw[bb][67], r1 = raw[bb][68], r2 = raw[bb][69];
            float mx = fmaxf(r0, fmaxf(r1, r2));
            float e0 = __expf(r0 - mx), e1 = __expf(r1 - mx), e2 = __expf(r2 - mx);
            float is = 1.f / (e0 + e1 + e2);
            g_params[b * 8 + 4] = e0 * is;
            g_params[b * 8 + 5] = e1 * is;
            g_params[b * 8 + 6] = e2 * is;
        }
    }
}

// ======================================================================
// Kernel 2: HMMA bf16 3-split GEMM. CTA tile 64(b) x 128(n), K=64.
// D = Ahi*Bhi + Ahi*Blo + Alo*Bhi. Epilogue: E = exp(D*sb[b]*inv_mn[n]).
// ======================================================================
#define RSTRIDE 144
#define OFF_A_HI 0
#define OFF_A_LO (64 * RSTRIDE)
#define OFF_B_HI (2 * 64 * RSTRIDE)
#define OFF_B_LO (OFF_B_HI + 128 * RSTRIDE)
#define OFF_INV  (OFF_B_LO + 128 * RSTRIDE)
#define OFF_SBS  (OFF_INV + 512)
#define SMEM_GEMM (OFF_SBS + 256)

__global__ void __launch_bounds__(128) k_gemm_hmma() {
    extern __shared__ char sm[];
    uint32_t sbase = smem_u32(sm);
    int t = threadIdx.x;
    int lane = t & 31, wid = t >> 5;
    int n0 = blockIdx.x * 128;
    int b0 = blockIdx.y * 64;

    {
        const uint4* sa_hi = (const uint4*)(g_khi + (size_t)b0 * M_);
        const uint4* sa_lo = (const uint4*)(g_klo + (size_t)b0 * M_);
        #pragma unroll
        for (int it = 0; it < 4; ++it) {
            int idx = t + it * 128;
            int r = idx >> 3, c = idx & 7;
            *(uint4*)(sm + OFF_A_HI + r * RSTRIDE + c * 16) = sa_hi[idx];
            *(uint4*)(sm + OFF_A_LO + r * RSTRIDE + c * 16) = sa_lo[idx];
        }
        const uint4* sb_hi = (const uint4*)(g_mhi + (size_t)n0 * M_);
        const uint4* sb_lo = (const uint4*)(g_mlo + (size_t)n0 * M_);
        #pragma unroll
        for (int it = 0; it < 8; ++it) {
            int idx = t + it * 128;
            int r = idx >> 3, c = idx & 7;
            *(uint4*)(sm + OFF_B_HI + r * RSTRIDE + c * 16) = sb_hi[idx];
            *(uint4*)(sm + OFF_B_LO + r * RSTRIDE + c * 16) = sb_lo[idx];
        }
        if (t < 64) {
            ((float*)(sm + OFF_INV))[t]      = g_inv_mn[n0 + t];
            ((float*)(sm + OFF_INV))[t + 64] = g_inv_mn[n0 + 64 + t];
            ((float*)(sm + OFF_SBS))[t]      = g_sb[b0 + t];
        }
    }
    __syncthreads();

    int wm = (wid >> 1) * 32;
    int wn = (wid & 1) * 64;
    int ltile = lane >> 3, lr = lane & 7;

    float acc[2][8][4];
    #pragma unroll
    for (int mi = 0; mi < 2; ++mi)
        #pragma unroll
        for (int nb = 0; nb < 8; ++nb)
            #pragma unroll
            for (int q = 0; q < 4; ++q) acc[mi][nb][q] = 0.f;

    #pragma unroll
    for (int pass = 0; pass < 3; ++pass) {
        uint32_t aOff = (pass == 2) ? OFF_A_LO : OFF_A_HI;
        uint32_t bOff = (pass == 1) ? OFF_B_LO : OFF_B_HI;
        #pragma unroll
        for (int ks = 0; ks < 4; ++ks) {
            uint32_t a[2][4];
            #pragma unroll
            for (int mi = 0; mi < 2; ++mi) {
                int rowA = wm + mi * 16 + (ltile & 1) * 8 + lr;
                int col16 = ks * 2 + (ltile >> 1);
                ldsm_x4(a[mi][0], a[mi][1], a[mi][2], a[mi][3],
                        sbase + aOff + rowA * RSTRIDE + col16 * 16);
            }
            uint32_t bfr[8][2];
            #pragma unroll
            for (int np = 0; np < 4; ++np) {
                int rowB = wn + np * 16 + (ltile >> 1) * 8 + lr;
                int col16 = ks * 2 + (ltile & 1);
                ldsm_x4(bfr[2 * np][0], bfr[2 * np][1], bfr[2 * np + 1][0], bfr[2 * np + 1][1],
                        sbase + bOff + rowB * RSTRIDE + col16 * 16);
            }
            #pragma unroll
            for (int mi = 0; mi < 2; ++mi)
                #pragma unroll
                for (int nb = 0; nb < 8; ++nb)
                    mma16816(acc[mi][nb], a[mi][0], a[mi][1], a[mi][2], a[mi][3],
                             bfr[nb][0], bfr[nb][1]);
        }
    }

    const float* inv_s = (const float*)(sm + OFF_INV);
    const float* sb_s  = (const float*)(sm + OFF_SBS);
    int r0 = lane >> 2, c0 = (lane & 3) * 2;
    #pragma unroll
    for (int mi = 0; mi < 2; ++mi) {
        int bl0 = wm + mi * 16 + r0;
        float s0 = sb_s[bl0], s1 = sb_s[bl0 + 8];
        float* d0 = &g_E[(size_t)(b0 + bl0) * N_ + n0];
        float* d1 = &g_E[(size_t)(b0 + bl0 + 8) * N_ + n0];
        #pragma unroll
        for (int nb = 0; nb < 8; ++nb) {
            int nl = wn + nb * 8 + c0;
            float i0 = inv_s[nl], i1 = inv_s[nl + 1];
            float2 e0, e1;
            e0.x = __expf(acc[mi][nb][0] * s0 * i0);
            e0.y = __expf(acc[mi][nb][1] * s0 * i1);
            e1.x = __expf(acc[mi][nb][2] * s1 * i0);
            e1.y = __expf(acc[mi][nb][3] * s1 * i1);
            *(float2*)(d0 + nl) = e0;
            *(float2*)(d1 + nl) = e1;
        }
    }
}

// ======================================================================
// Kernel 3: per-row fused tail (streaming, low-register).
// ======================================================================
__device__ __forceinline__ float blockReduceSum(float v, float* red) {
    int lane = threadIdx.x & 31, wid = threadIdx.x >> 5;
    #pragma unroll
    for (int o = 16; o; o >>= 1) v += __shfl_down_sync(0xffffffffu, v, o);
    if (lane == 0) red[wid] = v;
    __syncthreads();
    if (wid == 0) {
        float x = (lane < 16) ? red[lane] : 0.f;
        #pragma unroll
        for (int o = 8; o; o >>= 1) x += __shfl_down_sync(0xffffffffu, x, o);
        if (lane == 0) red[16] = x;
    }
    __syncthreads();
    return red[16];
}

__global__ void __launch_bounds__(512, 3) k_row(const float* __restrict__ w_tm1,
                                                float* __restrict__ out) {
    extern __shared__ float swg[];
    __shared__ float red[17];
    __shared__ float bnd[8];
    int t = threadIdx.x;
    int b = blockIdx.x;
    const float4* Erow = (const float4*)&g_E[(size_t)b * N_];
    const float4* Wrow = (const float4*)&w_tm1[(size_t)b * N_];
    float4* Orow = (float4*)&out[(size_t)b * N_];

    float se = 0.f;
    #pragma unroll
    for (int i = 0; i < 8; ++i) {
        int p = i * 512 + t;
        float4 e = Erow[p];
        *(float4*)&swg[p * 4] = e;
        se += e.x + e.y + e.z + e.w;
    }
    float inv_e = 1.0f / blockReduceSum(se, red);

    float g     = g_params[b * 8 + 2];
    float gamma = g_params[b * 8 + 3];
    float s0    = g_params[b * 8 + 4];
    float s1    = g_params[b * 8 + 5];
    float s2    = g_params[b * 8 + 6];
    float gs = g * inv_e, gi = 1.f - g;

    #pragma unroll
    for (int i = 0; i < 8; ++i) {
        int p = i * 512 + t;
        float4 e = *(float4*)&swg[p * 4];
        float4 wt = Wrow[p];
        float4 wg;
        wg.x = gs * e.x + gi * wt.x;
        wg.y = gs * e.y + gi * wt.y;
        wg.z = gs * e.z + gi * wt.z;
        wg.w = gs * e.w + gi * wt.w;
        *(float4*)&swg[p * 4] = wg;
    }
    __syncthreads();
    if (t < 8) bnd[t] = (t == 0) ? 0.f : swg[t * 2048 - 1];
    __syncthreads();

    float sw = 0.f;
    #pragma unroll
    for (int i = 0; i < 8; ++i) {
        int w0 = (i * 512 + t) * 4;
        float xm = (t == 0) ? bnd[i] : swg[w0 - 1];
        float4 x = *(float4*)&swg[w0];
        float xp = (w0 + 4 == N_) ? 0.f : swg[w0 + 4];
        float t0 = s0 * xm  + s1 * x.x + s2 * x.y;
        float t1 = s0 * x.x + s1 * x.y + s2 * x.z;
        float t2 = s0 * x.y + s1 * x.z + s2 * x.w;
        float t3 = s0 * x.z + s1 * x.w + s2 * xp;
        float p0 = __powf(t0 + 1e-6f, gamma);
        float p1 = __powf(t1 + 1e-6f, gamma);
        float p2 = __powf(t2 + 1e-6f, gamma);
        float p3 = __powf(t3 + 1e-6f, gamma);
        __syncthreads();
        *(float4*)&swg[w0] = make_float4(p0, p1, p2, p3);
        sw += p0 + p1 + p2 + p3;
    }
    float inv_w = 1.0f / blockReduceSum(sw, red);

    #pragma unroll
    for (int i = 0; i < 8; ++i) {
        int p = i * 512 + t;
        float4 x = *(float4*)&swg[p * 4];
        Orow[p] = make_float4(x.x * inv_w, x.y * inv_w, x.z * inv_w, x.w * inv_w);
    }
}

// ======================================================================
extern "C" void kernel_launch(void* const* d_in, const int* in_sizes, int n_in,
                              void* d_out, int out_size) {
    const float* h_t   = (const float*)d_in[0];
    const float* w_tm1 = (const float*)d_in[1];
    const float* m_t   = (const float*)d_in[2];
    const float* Wk    = (const float*)d_in[3];
    const float* bk    = (const float*)d_in[4];
    const float* Wb    = (const float*)d_in[5];
    const float* bb    = (const float*)d_in[6];
    const float* Wg    = (const float*)d_in[7];
    const float* bg    = (const float*)d_in[8];
    const float* Ws    = (const float*)d_in[9];
    const float* bs    = (const float*)d_in[10];
    const float* Wm    = (const float*)d_in[11];
    const float* bm    = (const float*)d_in[12];
    float* out = (float*)d_out;

    cudaFuncSetAttribute(k_gemm_hmma, cudaFuncAttributeMaxDynamicSharedMemorySize, SMEM_GEMM);
    cudaFuncSetAttribute(k_row,       cudaFuncAttributeMaxDynamicSharedMemorySize, 65536);

    k_prep<<<512, 256>>>(m_t, h_t, Wk, bk, Wb, bb, Wg, bg, Ws, bs, Wm, bm);
    k_gemm_hmma<<<dim3(N_ / 128, B_ / 64), 128, SMEM_GEMM>>>();
    k_row<<<B_, 512, 65536>>>(w_tm1, out);
}

// round 6
// speedup vs baseline: 1.5915x; 1.0360x over previous
#include <cuda_runtime.h>
#include <cuda_bf16.h>
#include <cstdint>

#define B_ 1024
#define H_ 512
#define N_ 16384
#define M_ 64

// ---------------- scratch (static device globals) ----------------
__device__ __nv_bfloat16 g_mhi[N_ * M_];   // bf16 hi of m_t [N][64]
__device__ __nv_bfloat16 g_mlo[N_ * M_];   // bf16 lo of m_t
__device__ float g_inv_mn[N_];             // 1/||m_t[n]||
__device__ __nv_bfloat16 g_khi[B_ * M_];   // bf16 hi of k_t [B][64]
__device__ __nv_bfloat16 g_klo[B_ * M_];
__device__ float g_sb[B_];                 // beta / ||k||
__device__ float g_params[B_ * 8];         // g, gamma, s0,s1,s2
__device__ float g_E[B_ * N_];             // exp(scores) fp32 (64 MB)

__device__ __forceinline__ uint32_t smem_u32(const void* p) {
    uint32_t a;
    asm("{ .reg .u64 t; cvta.to.shared.u64 t, %1; cvt.u32.u64 %0, t; }" : "=r"(a) : "l"(p));
    return a;
}
__device__ __forceinline__ void ldsm_x4(uint32_t& r0, uint32_t& r1, uint32_t& r2, uint32_t& r3,
                                        uint32_t addr) {
    asm volatile("ldmatrix.sync.aligned.m8n8.x4.shared.b16 {%0,%1,%2,%3}, [%4];"
                 : "=r"(r0), "=r"(r1), "=r"(r2), "=r"(r3) : "r"(addr));
}
__device__ __forceinline__ void mma16816(float* c, uint32_t a0, uint32_t a1, uint32_t a2,
                                         uint32_t a3, uint32_t b0, uint32_t b1) {
    asm volatile(
        "mma.sync.aligned.m16n8k16.row.col.f32.bf16.bf16.f32 "
        "{%0,%1,%2,%3}, {%4,%5,%6,%7}, {%8,%9}, {%0,%1,%2,%3};"
        : "+f"(c[0]), "+f"(c[1]), "+f"(c[2]), "+f"(c[3])
        : "r"(a0), "r"(a1), "r"(a2), "r"(a3), "r"(b0), "r"(b1));
}

// ======================================================================
// Kernel 1 (fused): blocks [0,256): m prep  |  blocks [256,384): proj
// proj: 8 batch rows / CTA, float4 W loads, 32 FMAs per load, u64-packed
// shuffle reduction.
// ======================================================================
__global__ void __launch_bounds__(256) k_prep(
    const float* __restrict__ m,
    const float* __restrict__ h,
    const float* __restrict__ Wk, const float* __restrict__ bk,
    const float* __restrict__ Wb, const float* __restrict__ bbp,
    const float* __restrict__ Wg, const float* __restrict__ bgp,
    const float* __restrict__ Ws, const float* __restrict__ bsp,
    const float* __restrict__ Wm, const float* __restrict__ bmp) {
    int t = threadIdx.x;
    if (blockIdx.x < 256) {
        // ---- m prep: bf16 hi/lo split + 1/row-norm; 64 rows / block ----
        int row = blockIdx.x * 64 + (t >> 2);
        int part = t & 3;
        const float4* src = (const float4*)(m + row * M_ + part * 16);
        float v[16];
        #pragma unroll
        for (int i = 0; i < 4; ++i) {
            float4 f = src[i];
            v[4 * i] = f.x; v[4 * i + 1] = f.y; v[4 * i + 2] = f.z; v[4 * i + 3] = f.w;
        }
        float s = 0.f;
        unsigned int ph[8], pl[8];
        #pragma unroll
        for (int i = 0; i < 8; ++i) {
            float a = v[2 * i], b = v[2 * i + 1];
            s += a * a + b * b;
            __nv_bfloat16 ha = __float2bfloat16(a), hb = __float2bfloat16(b);
            __nv_bfloat16 la = __float2bfloat16(a - __bfloat162float(ha));
            __nv_bfloat16 lb = __float2bfloat16(b - __bfloat162float(hb));
            ph[i] = (unsigned int)__bfloat16_as_ushort(ha) | ((unsigned int)__bfloat16_as_ushort(hb) << 16);
            pl[i] = (unsigned int)__bfloat16_as_ushort(la) | ((unsigned int)__bfloat16_as_ushort(lb) << 16);
        }
        uint4* dh = (uint4*)(g_mhi + row * M_ + part * 16);
        uint4* dl = (uint4*)(g_mlo + row * M_ + part * 16);
        dh[0] = make_uint4(ph[0], ph[1], ph[2], ph[3]);
        dh[1] = make_uint4(ph[4], ph[5], ph[6], ph[7]);
        dl[0] = make_uint4(pl[0], pl[1], pl[2], pl[3]);
        dl[1] = make_uint4(pl[4], pl[5], pl[6], pl[7]);
        s += __shfl_down_sync(0xffffffffu, s, 2);
        s += __shfl_down_sync(0xffffffffu, s, 1);
        if (part == 0) g_inv_mn[row] = rsqrtf(fmaxf(s, 1e-24f));
        return;
    }
    // ---- projections: 8 batch rows per CTA ----
    __shared__ float hs[8][512];
    __shared__ float raw[8][72];
    __shared__ float sq[8][64];
    int lane = t & 31, wid = t >> 5;
    int b0 = (blockIdx.x - 256) * 8;

    // load 8 h rows (1024 float4s, 4 iters)
    #pragma unroll
    for (int it = 0; it < 4; ++it) {
        int idx = t + it * 256;                  // 0..1023
        int r = idx >> 7, c = (idx & 127) * 4;
        *(float4*)&hs[r][c] = *(const float4*)&h[(b0 + r) * H_ + c];
    }
    __syncthreads();

    for (int j = wid; j < 70; j += 8) {
        const float* Wr; float bias;
        if (j < 64)       { Wr = Wk + j * H_;        bias = bk[j]; }
        else if (j == 64) { Wr = Wb;                 bias = bbp[0]; }
        else if (j == 65) { Wr = Wg;                 bias = bgp[0]; }
        else if (j == 66) { Wr = Wm;                 bias = bmp[0]; }
        else              { Wr = Ws + (j - 67) * H_; bias = bsp[j - 67]; }
        float acc[8];
        #pragma unroll
        for (int r = 0; r < 8; ++r) acc[r] = 0.f;
        const float4* Wr4 = (const float4*)Wr;
        #pragma unroll
        for (int it = 0; it < 4; ++it) {
            int i4 = lane + it * 32;             // float4 index, 0..127
            float4 w = Wr4[i4];
            #pragma unroll
            for (int r = 0; r < 8; ++r) {
                float4 hv = *(const float4*)&hs[r][i4 * 4];
                acc[r] += w.x * hv.x + w.y * hv.y + w.z * hv.z + w.w * hv.w;
            }
        }
        // u64-packed butterfly-free down reduce: pack pairs
        unsigned long long p0, p1, p2, p3;
        asm("mov.b64 %0, {%1, %2};" : "=l"(p0) : "f"(acc[0]), "f"(acc[1]));
        asm("mov.b64 %0, {%1, %2};" : "=l"(p1) : "f"(acc[2]), "f"(acc[3]));
        asm("mov.b64 %0, {%1, %2};" : "=l"(p2) : "f"(acc[4]), "f"(acc[5]));
        asm("mov.b64 %0, {%1, %2};" : "=l"(p3) : "f"(acc[6]), "f"(acc[7]));
        #pragma unroll
        for (int o = 16; o; o >>= 1) {
            unsigned long long q0 = __shfl_down_sync(0xffffffffu, p0, o);
            unsigned long long q1 = __shfl_down_sync(0xffffffffu, p1, o);
            unsigned long long q2 = __shfl_down_sync(0xffffffffu, p2, o);
            unsigned long long q3 = __shfl_down_sync(0xffffffffu, p3, o);
            float ax, ay, bx, by;
            asm("mov.b64 {%0, %1}, %2;" : "=f"(ax), "=f"(ay) : "l"(p0));
            asm("mov.b64 {%0, %1}, %2;" : "=f"(bx), "=f"(by) : "l"(q0));
            ax += bx; ay += by;
            asm("mov.b64 %0, {%1, %2};" : "=l"(p0) : "f"(ax), "f"(ay));
            asm("mov.b64 {%0, %1}, %2;" : "=f"(ax), "=f"(ay) : "l"(p1));
            asm("mov.b64 {%0, %1}, %2;" : "=f"(bx), "=f"(by) : "l"(q1));
            ax += bx; ay += by;
            asm("mov.b64 %0, {%1, %2};" : "=l"(p1) : "f"(ax), "f"(ay));
            asm("mov.b64 {%0, %1}, %2;" : "=f"(ax), "=f"(ay) : "l"(p2));
            asm("mov.b64 {%0, %1}, %2;" : "=f"(bx), "=f"(by) : "l"(q2));
            ax += bx; ay += by;
            asm("mov.b64 %0, {%1, %2};" : "=l"(p2) : "f"(ax), "f"(ay));
            asm("mov.b64 {%0, %1}, %2;" : "=f"(ax), "=f"(ay) : "l"(p3));
            asm("mov.b64 {%0, %1}, %2;" : "=f"(bx), "=f"(by) : "l"(q3));
            ax += bx; ay += by;
            asm("mov.b64 %0, {%1, %2};" : "=l"(p3) : "f"(ax), "f"(ay));
        }
        if (lane == 0) {
            float r0, r1;
            asm("mov.b64 {%0, %1}, %2;" : "=f"(r0), "=f"(r1) : "l"(p0));
            raw[0][j] = r0 + bias; raw[1][j] = r1 + bias;
            asm("mov.b64 {%0, %1}, %2;" : "=f"(r0), "=f"(r1) : "l"(p1));
            raw[2][j] = r0 + bias; raw[3][j] = r1 + bias;
            asm("mov.b64 {%0, %1}, %2;" : "=f"(r0), "=f"(r1) : "l"(p2));
            raw[4][j] = r0 + bias; raw[5][j] = r1 + bias;
            asm("mov.b64 {%0, %1}, %2;" : "=f"(r0), "=f"(r1) : "l"(p3));
            raw[6][j] = r0 + bias; raw[7][j] = r1 + bias;
        }
    }
    __syncthreads();

    // k store + squares: 512 elems (8 rows x 64), 256 threads, 2 each
    #pragma unroll
    for (int it = 0; it < 2; ++it) {
        int idx = t + it * 256;
        int bb = idx >> 6, col = idx & 63;
        int b = b0 + bb;
        float kv = fminf(fmaxf(raw[bb][col], 0.f), 1.f);
        __nv_bfloat16 hv = __float2bfloat16(kv);
        __nv_bfloat16 lv = __float2bfloat16(kv - __bfloat162float(hv));
        g_khi[b * M_ + col] = hv;
        g_klo[b * M_ + col] = lv;
        sq[bb][col] = kv * kv;
    }
    __syncthreads();

    {
        int bb = wid, b = b0 + bb;   // 8 warps, one row each
        float v = sq[bb][lane] + sq[bb][lane + 32];
        #pragma unroll
        for (int o = 16; o; o >>= 1) v += __shfl_down_sync(0xffffffffu, v, o);
        if (lane == 0) {
            float beta = fmaxf(raw[bb][64], 0.f);
            float kn = sqrtf(v);
            g_sb[b] = beta * kn / (kn * kn + 1e-12f);                 // beta/||k||
            g_params[b * 8 + 2] = fminf(fmaxf(raw[bb][65], 0.f), 1.f);
            g_params[b * 8 + 3] = 1.f + fmaxf(raw[bb][66], 0.f);
            float r0 = raw[bb][67], r1 = raw[bb][68], r2 = raw[bb][69];
            float mx = fmaxf(r0, fmaxf(r1, r2));
            float e0 = __expf(r0 - mx), e1 = __expf(r1 - mx), e2 = __expf(r2 - mx);
            float is = 1.f / (e0 + e1 + e2);
            g_params[b * 8 + 4] = e0 * is;
            g_params[b * 8 + 5] = e1 * is;
            g_params[b * 8 + 6] = e2 * is;
        }
    }
}

// ======================================================================
// Kernel 2: HMMA bf16 3-split GEMM. CTA tile 64(b) x 128(n), K=64.
// D = Ahi*Bhi + Ahi*Blo + Alo*Bhi. Epilogue: E = exp(D*sb[b]*inv_mn[n]).
// ======================================================================
#define RSTRIDE 144
#define OFF_A_HI 0
#define OFF_A_LO (64 * RSTRIDE)
#define OFF_B_HI (2 * 64 * RSTRIDE)
#define OFF_B_LO (OFF_B_HI + 128 * RSTRIDE)
#define OFF_INV  (OFF_B_LO + 128 * RSTRIDE)
#define OFF_SBS  (OFF_INV + 512)
#define SMEM_GEMM (OFF_SBS + 256)

__global__ void __launch_bounds__(128) k_gemm_hmma() {
    extern __shared__ char sm[];
    uint32_t sbase = smem_u32(sm);
    int t = threadIdx.x;
    int lane = t & 31, wid = t >> 5;
    int n0 = blockIdx.x * 128;
    int b0 = blockIdx.y * 64;

    {
        const uint4* sa_hi = (const uint4*)(g_khi + (size_t)b0 * M_);
        const uint4* sa_lo = (const uint4*)(g_klo + (size_t)b0 * M_);
        #pragma unroll
        for (int it = 0; it < 4; ++it) {
            int idx = t + it * 128;
            int r = idx >> 3, c = idx & 7;
            *(uint4*)(sm + OFF_A_HI + r * RSTRIDE + c * 16) = sa_hi[idx];
            *(uint4*)(sm + OFF_A_LO + r * RSTRIDE + c * 16) = sa_lo[idx];
        }
        const uint4* sb_hi = (const uint4*)(g_mhi + (size_t)n0 * M_);
        const uint4* sb_lo = (const uint4*)(g_mlo + (size_t)n0 * M_);
        #pragma unroll
        for (int it = 0; it < 8; ++it) {
            int idx = t + it * 128;
            int r = idx >> 3, c = idx & 7;
            *(uint4*)(sm + OFF_B_HI + r * RSTRIDE + c * 16) = sb_hi[idx];
            *(uint4*)(sm + OFF_B_LO + r * RSTRIDE + c * 16) = sb_lo[idx];
        }
        if (t < 64) {
            ((float*)(sm + OFF_INV))[t]      = g_inv_mn[n0 + t];
            ((float*)(sm + OFF_INV))[t + 64] = g_inv_mn[n0 + 64 + t];
            ((float*)(sm + OFF_SBS))[t]      = g_sb[b0 + t];
        }
    }
    __syncthreads();

    int wm = (wid >> 1) * 32;
    int wn = (wid & 1) * 64;
    int ltile = lane >> 3, lr = lane & 7;

    float acc[2][8][4];
    #pragma unroll
    for (int mi = 0; mi < 2; ++mi)
        #pragma unroll
        for (int nb = 0; nb < 8; ++nb)
            #pragma unroll
            for (int q = 0; q < 4; ++q) acc[mi][nb][q] = 0.f;

    #pragma unroll
    for (int pass = 0; pass < 3; ++pass) {
        uint32_t aOff = (pass == 2) ? OFF_A_LO : OFF_A_HI;
        uint32_t bOff = (pass == 1) ? OFF_B_LO : OFF_B_HI;
        #pragma unroll
        for (int ks = 0; ks < 4; ++ks) {
            uint32_t a[2][4];
            #pragma unroll
            for (int mi = 0; mi < 2; ++mi) {
                int rowA = wm + mi * 16 + (ltile & 1) * 8 + lr;
                int col16 = ks * 2 + (ltile >> 1);
                ldsm_x4(a[mi][0], a[mi][1], a[mi][2], a[mi][3],
                        sbase + aOff + rowA * RSTRIDE + col16 * 16);
            }
            uint32_t bfr[8][2];
            #pragma unroll
            for (int np = 0; np < 4; ++np) {
                int rowB = wn + np * 16 + (ltile >> 1) * 8 + lr;
                int col16 = ks * 2 + (ltile & 1);
                ldsm_x4(bfr[2 * np][0], bfr[2 * np][1], bfr[2 * np + 1][0], bfr[2 * np + 1][1],
                        sbase + bOff + rowB * RSTRIDE + col16 * 16);
            }
            #pragma unroll
            for (int mi = 0; mi < 2; ++mi)
                #pragma unroll
                for (int nb = 0; nb < 8; ++nb)
                    mma16816(acc[mi][nb], a[mi][0], a[mi][1], a[mi][2], a[mi][3],
                             bfr[nb][0], bfr[nb][1]);
        }
    }

    const float* inv_s = (const float*)(sm + OFF_INV);
    const float* sb_s  = (const float*)(sm + OFF_SBS);
    int r0 = lane >> 2, c0 = (lane & 3) * 2;
    #pragma unroll
    for (int mi = 0; mi < 2; ++mi) {
        int bl0 = wm + mi * 16 + r0;
        float s0 = sb_s[bl0], s1 = sb_s[bl0 + 8];
        float* d0 = &g_E[(size_t)(b0 + bl0) * N_ + n0];
        float* d1 = &g_E[(size_t)(b0 + bl0 + 8) * N_ + n0];
        #pragma unroll
        for (int nb = 0; nb < 8; ++nb) {
            int nl = wn + nb * 8 + c0;
            float i0 = inv_s[nl], i1 = inv_s[nl + 1];
            float2 e0, e1;
            e0.x = __expf(acc[mi][nb][0] * s0 * i0);
            e0.y = __expf(acc[mi][nb][1] * s0 * i1);
            e1.x = __expf(acc[mi][nb][2] * s1 * i0);
            e1.y = __expf(acc[mi][nb][3] * s1 * i1);
            *(float2*)(d0 + nl) = e0;
            *(float2*)(d1 + nl) = e1;
        }
    }
}

// ======================================================================
// Kernel 3: per-row fused tail (streaming, low-register).
// ======================================================================
__device__ __forceinline__ float blockReduceSum(float v, float* red) {
    int lane = threadIdx.x & 31, wid = threadIdx.x >> 5;
    #pragma unroll
    for (int o = 16; o; o >>= 1) v += __shfl_down_sync(0xffffffffu, v, o);
    if (lane == 0) red[wid] = v;
    __syncthreads();
    if (wid == 0) {
        float x = (lane < 16) ? red[lane] : 0.f;
        #pragma unroll
        for (int o = 8; o; o >>= 1) x += __shfl_down_sync(0xffffffffu, x, o);
        if (lane == 0) red[16] = x;
    }
    __syncthreads();
    return red[16];
}

__global__ void __launch_bounds__(512, 3) k_row(const float* __restrict__ w_tm1,
                                                float* __restrict__ out) {
    extern __shared__ float swg[];
    __shared__ float red[17];
    __shared__ float bnd[8];
    int t = threadIdx.x;
    int b = blockIdx.x;
    const float4* Erow = (const float4*)&g_E[(size_t)b * N_];
    const float4* Wrow = (const float4*)&w_tm1[(size_t)b * N_];
    float4* Orow = (float4*)&out[(size_t)b * N_];

    float se = 0.f;
    #pragma unroll
    for (int i = 0; i < 8; ++i) {
        int p = i * 512 + t;
        float4 e = Erow[p];
        *(float4*)&swg[p * 4] = e;
        se += e.x + e.y + e.z + e.w;
    }
    float inv_e = 1.0f / blockReduceSum(se, red);

    float g     = g_params[b * 8 + 2];
    float gamma = g_params[b * 8 + 3];
    float s0    = g_params[b * 8 + 4];
    float s1    = g_params[b * 8 + 5];
    float s2    = g_params[b * 8 + 6];
    float gs = g * inv_e, gi = 1.f - g;

    #pragma unroll
    for (int i = 0; i < 8; ++i) {
        int p = i * 512 + t;
        float4 e = *(float4*)&swg[p * 4];
        float4 wt = Wrow[p];
        float4 wg;
        wg.x = gs * e.x + gi * wt.x;
        wg.y = gs * e.y + gi * wt.y;
        wg.z = gs * e.z + gi * wt.z;
        wg.w = gs * e.w + gi * wt.w;
        *(float4*)&swg[p * 4] = wg;
    }
    __syncthreads();
    if (t < 8) bnd[t] = (t == 0) ? 0.f : swg[t * 2048 - 1];
    __syncthreads();

    float sw = 0.f;
    #pragma unroll
    for (int i = 0; i < 8; ++i) {
        int w0 = (i * 512 + t) * 4;
        float xm = (t == 0) ? bnd[i] : swg[w0 - 1];
        float4 x = *(float4*)&swg[w0];
        float xp = (w0 + 4 == N_) ? 0.f : swg[w0 + 4];
        float t0 = s0 * xm  + s1 * x.x + s2 * x.y;
        float t1 = s0 * x.x + s1 * x.y + s2 * x.z;
        float t2 = s0 * x.y + s1 * x.z + s2 * x.w;
        float t3 = s0 * x.z + s1 * x.w + s2 * xp;
        float p0 = __powf(t0 + 1e-6f, gamma);
        float p1 = __powf(t1 + 1e-6f, gamma);
        float p2 = __powf(t2 + 1e-6f, gamma);
        float p3 = __powf(t3 + 1e-6f, gamma);
        __syncthreads();
        *(float4*)&swg[w0] = make_float4(p0, p1, p2, p3);
        sw += p0 + p1 + p2 + p3;
    }
    float inv_w = 1.0f / blockReduceSum(sw, red);

    #pragma unroll
    for (int i = 0; i < 8; ++i) {
        int p = i * 512 + t;
        float4 x = *(float4*)&swg[p * 4];
        Orow[p] = make_float4(x.x * inv_w, x.y * inv_w, x.z * inv_w, x.w * inv_w);
    }
}

// ======================================================================
extern "C" void kernel_launch(void* const* d_in, const int* in_sizes, int n_in,
                              void* d_out, int out_size) {
    const float* h_t   = (const float*)d_in[0];
    const float* w_tm1 = (const float*)d_in[1];
    const float* m_t   = (const float*)d_in[2];
    const float* Wk    = (const float*)d_in[3];
    const float* bk    = (const float*)d_in[4];
    const float* Wb    = (const float*)d_in[5];
    const float* bb    = (const float*)d_in[6];
    const float* Wg    = (const float*)d_in[7];
    const float* bg    = (const float*)d_in[8];
    const float* Ws    = (const float*)d_in[9];
    const float* bs    = (const float*)d_in[10];
    const float* Wm    = (const float*)d_in[11];
    const float* bm    = (const float*)d_in[12];
    float* out = (float*)d_out;

    cudaFuncSetAttribute(k_gemm_hmma, cudaFuncAttributeMaxDynamicSharedMemorySize, SMEM_GEMM);
    cudaFuncSetAttribute(k_row,       cudaFuncAttributeMaxDynamicSharedMemorySize, 65536);

    k_prep<<<384, 256>>>(m_t, h_t, Wk, bk, Wb, bb, Wg, bg, Ws, bs, Wm, bm);
    k_gemm_hmma<<<dim3(N_ / 128, B_ / 64), 128, SMEM_GEMM>>>();
    k_row<<<B_, 512, 65536>>>(w_tm1, out);
}

// round 7
// speedup vs baseline: 1.5921x; 1.0003x over previous
#include <cuda_runtime.h>
#include <cuda_bf16.h>
#include <cstdint>

#define B_ 1024
#define H_ 512
#define N_ 16384
#define M_ 64

// ---------------- scratch (static device globals) ----------------
__device__ __nv_bfloat16 g_mhi[N_ * M_];   // bf16 hi of m_t [N][64]
__device__ __nv_bfloat16 g_mlo[N_ * M_];   // bf16 lo of m_t
__device__ float g_inv_mn[N_];             // 1/||m_t[n]||
__device__ __nv_bfloat16 g_khi[B_ * M_];   // bf16 hi of k_t [B][64]
__device__ __nv_bfloat16 g_klo[B_ * M_];
__device__ float g_sb[B_];                 // beta / ||k||
__device__ float g_params[B_ * 8];         // g, gamma, s0,s1,s2
__device__ float g_E[B_ * N_];             // exp(scores) fp32 (64 MB)

__device__ __forceinline__ uint32_t smem_u32(const void* p) {
    uint32_t a;
    asm("{ .reg .u64 t; cvta.to.shared.u64 t, %1; cvt.u32.u64 %0, t; }" : "=r"(a) : "l"(p));
    return a;
}
__device__ __forceinline__ void ldsm_x4(uint32_t& r0, uint32_t& r1, uint32_t& r2, uint32_t& r3,
                                        uint32_t addr) {
    asm volatile("ldmatrix.sync.aligned.m8n8.x4.shared.b16 {%0,%1,%2,%3}, [%4];"
                 : "=r"(r0), "=r"(r1), "=r"(r2), "=r"(r3) : "r"(addr));
}
__device__ __forceinline__ void mma16816(float* c, uint32_t a0, uint32_t a1, uint32_t a2,
                                         uint32_t a3, uint32_t b0, uint32_t b1) {
    asm volatile(
        "mma.sync.aligned.m16n8k16.row.col.f32.bf16.bf16.f32 "
        "{%0,%1,%2,%3}, {%4,%5,%6,%7}, {%8,%9}, {%0,%1,%2,%3};"
        : "+f"(c[0]), "+f"(c[1]), "+f"(c[2]), "+f"(c[3])
        : "r"(a0), "r"(a1), "r"(a2), "r"(a3), "r"(b0), "r"(b1));
}

// ======================================================================
// Kernel 1 (fused): blocks [0,256): m prep  |  blocks [256,512): proj
// proj: 4 batch rows / CTA (256 CTAs), float4 W loads (16 FMA/load),
// u64-packed shuffle reduction.
// ======================================================================
__global__ void __launch_bounds__(256) k_prep(
    const float* __restrict__ m,
    const float* __restrict__ h,
    const float* __restrict__ Wk, const float* __restrict__ bk,
    const float* __restrict__ Wb, const float* __restrict__ bbp,
    const float* __restrict__ Wg, const float* __restrict__ bgp,
    const float* __restrict__ Ws, const float* __restrict__ bsp,
    const float* __restrict__ Wm, const float* __restrict__ bmp) {
    int t = threadIdx.x;
    if (blockIdx.x < 256) {
        // ---- m prep: bf16 hi/lo split + 1/row-norm; 64 rows / block ----
        int row = blockIdx.x * 64 + (t >> 2);
        int part = t & 3;
        const float4* src = (const float4*)(m + row * M_ + part * 16);
        float v[16];
        #pragma unroll
        for (int i = 0; i < 4; ++i) {
            float4 f = src[i];
            v[4 * i] = f.x; v[4 * i + 1] = f.y; v[4 * i + 2] = f.z; v[4 * i + 3] = f.w;
        }
        float s = 0.f;
        unsigned int ph[8], pl[8];
        #pragma unroll
        for (int i = 0; i < 8; ++i) {
            float a = v[2 * i], b = v[2 * i + 1];
            s += a * a + b * b;
            __nv_bfloat16 ha = __float2bfloat16(a), hb = __float2bfloat16(b);
            __nv_bfloat16 la = __float2bfloat16(a - __bfloat162float(ha));
            __nv_bfloat16 lb = __float2bfloat16(b - __bfloat162float(hb));
            ph[i] = (unsigned int)__bfloat16_as_ushort(ha) | ((unsigned int)__bfloat16_as_ushort(hb) << 16);
            pl[i] = (unsigned int)__bfloat16_as_ushort(la) | ((unsigned int)__bfloat16_as_ushort(lb) << 16);
        }
        uint4* dh = (uint4*)(g_mhi + row * M_ + part * 16);
        uint4* dl = (uint4*)(g_mlo + row * M_ + part * 16);
        dh[0] = make_uint4(ph[0], ph[1], ph[2], ph[3]);
        dh[1] = make_uint4(ph[4], ph[5], ph[6], ph[7]);
        dl[0] = make_uint4(pl[0], pl[1], pl[2], pl[3]);
        dl[1] = make_uint4(pl[4], pl[5], pl[6], pl[7]);
        s += __shfl_down_sync(0xffffffffu, s, 2);
        s += __shfl_down_sync(0xffffffffu, s, 1);
        if (part == 0) g_inv_mn[row] = rsqrtf(fmaxf(s, 1e-24f));
        return;
    }
    // ---- projections: 4 batch rows per CTA, 256 proj CTAs ----
    __shared__ float hs[4][512];
    __shared__ float raw[4][72];
    __shared__ float sq[4][64];
    int lane = t & 31, wid = t >> 5;
    int b0 = (blockIdx.x - 256) * 4;

    // load 4 h rows (512 float4s, 2 iters)
    #pragma unroll
    for (int it = 0; it < 2; ++it) {
        int idx = t + it * 256;                  // 0..511
        int r = idx >> 7, c = (idx & 127) * 4;
        *(float4*)&hs[r][c] = *(const float4*)&h[(b0 + r) * H_ + c];
    }
    __syncthreads();

    for (int j = wid; j < 70; j += 8) {
        const float* Wr; float bias;
        if (j < 64)       { Wr = Wk + j * H_;        bias = bk[j]; }
        else if (j == 64) { Wr = Wb;                 bias = bbp[0]; }
        else if (j == 65) { Wr = Wg;                 bias = bgp[0]; }
        else if (j == 66) { Wr = Wm;                 bias = bmp[0]; }
        else              { Wr = Ws + (j - 67) * H_; bias = bsp[j - 67]; }
        float acc[4];
        #pragma unroll
        for (int r = 0; r < 4; ++r) acc[r] = 0.f;
        const float4* Wr4 = (const float4*)Wr;
        #pragma unroll
        for (int it = 0; it < 4; ++it) {
            int i4 = lane + it * 32;             // float4 index, 0..127
            float4 w = Wr4[i4];
            #pragma unroll
            for (int r = 0; r < 4; ++r) {
                float4 hv = *(const float4*)&hs[r][i4 * 4];
                acc[r] += w.x * hv.x + w.y * hv.y + w.z * hv.z + w.w * hv.w;
            }
        }
        unsigned long long p0, p1;
        asm("mov.b64 %0, {%1, %2};" : "=l"(p0) : "f"(acc[0]), "f"(acc[1]));
        asm("mov.b64 %0, {%1, %2};" : "=l"(p1) : "f"(acc[2]), "f"(acc[3]));
        #pragma unroll
        for (int o = 16; o; o >>= 1) {
            unsigned long long q0 = __shfl_down_sync(0xffffffffu, p0, o);
            unsigned long long q1 = __shfl_down_sync(0xffffffffu, p1, o);
            float ax, ay, bx, by;
            asm("mov.b64 {%0, %1}, %2;" : "=f"(ax), "=f"(ay) : "l"(p0));
            asm("mov.b64 {%0, %1}, %2;" : "=f"(bx), "=f"(by) : "l"(q0));
            ax += bx; ay += by;
            asm("mov.b64 %0, {%1, %2};" : "=l"(p0) : "f"(ax), "f"(ay));
            asm("mov.b64 {%0, %1}, %2;" : "=f"(ax), "=f"(ay) : "l"(p1));
            asm("mov.b64 {%0, %1}, %2;" : "=f"(bx), "=f"(by) : "l"(q1));
            ax += bx; ay += by;
            asm("mov.b64 %0, {%1, %2};" : "=l"(p1) : "f"(ax), "f"(ay));
        }
        if (lane == 0) {
            float r0, r1;
            asm("mov.b64 {%0, %1}, %2;" : "=f"(r0), "=f"(r1) : "l"(p0));
            raw[0][j] = r0 + bias; raw[1][j] = r1 + bias;
            asm("mov.b64 {%0, %1}, %2;" : "=f"(r0), "=f"(r1) : "l"(p1));
            raw[2][j] = r0 + bias; raw[3][j] = r1 + bias;
        }
    }
    __syncthreads();

    // k store + squares: 256 elems (4 rows x 64) = 256 threads
    {
        int bb = t >> 6, col = t & 63;
        int b = b0 + bb;
        float kv = fminf(fmaxf(raw[bb][col], 0.f), 1.f);
        __nv_bfloat16 hv = __float2bfloat16(kv);
        __nv_bfloat16 lv = __float2bfloat16(kv - __bfloat162float(hv));
        g_khi[b * M_ + col] = hv;
        g_klo[b * M_ + col] = lv;
        sq[bb][col] = kv * kv;
    }
    __syncthreads();

    if (wid < 4) {
        int bb = wid, b = b0 + bb;
        float v = sq[bb][lane] + sq[bb][lane + 32];
        #pragma unroll
        for (int o = 16; o; o >>= 1) v += __shfl_down_sync(0xffffffffu, v, o);
        if (lane == 0) {
            float beta = fmaxf(raw[bb][64], 0.f);
            float kn = sqrtf(v);
            g_sb[b] = beta * kn / (kn * kn + 1e-12f);                 // beta/||k||
            g_params[b * 8 + 2] = fminf(fmaxf(raw[bb][65], 0.f), 1.f);
            g_params[b * 8 + 3] = 1.f + fmaxf(raw[bb][66], 0.f);
            float r0 = raw[bb][67], r1 = raw[bb][68], r2 = raw[bb][69];
            float mx = fmaxf(r0, fmaxf(r1, r2));
            float e0 = __expf(r0 - mx), e1 = __expf(r1 - mx), e2 = __expf(r2 - mx);
            float is = 1.f / (e0 + e1 + e2);
            g_params[b * 8 + 4] = e0 * is;
            g_params[b * 8 + 5] = e1 * is;
            g_params[b * 8 + 6] = e2 * is;
        }
    }
}

// ======================================================================
// Kernel 2: HMMA bf16 3-split GEMM. CTA tile 128(b) x 128(n), K=64,
// 256 threads (8 warps, each 32x64). D = Ahi*Bhi + Ahi*Blo + Alo*Bhi.
// Epilogue: E = exp(D*sb[b]*inv_mn[n]).
// ======================================================================
#define RSTRIDE 144
#define OFF_A_HI 0
#define OFF_A_LO (128 * RSTRIDE)
#define OFF_B_HI (2 * 128 * RSTRIDE)
#define OFF_B_LO (3 * 128 * RSTRIDE)
#define OFF_INV  (4 * 128 * RSTRIDE)                 // 128 floats
#define OFF_SBS  (OFF_INV + 512)                     // 128 floats
#define SMEM_GEMM (OFF_SBS + 512)

__global__ void __launch_bounds__(256) k_gemm_hmma() {
    extern __shared__ char sm[];
    uint32_t sbase = smem_u32(sm);
    int t = threadIdx.x;
    int lane = t & 31, wid = t >> 5;
    int n0 = blockIdx.x * 128;
    int b0 = blockIdx.y * 128;

    {
        const uint4* sa_hi = (const uint4*)(g_khi + (size_t)b0 * M_);
        const uint4* sa_lo = (const uint4*)(g_klo + (size_t)b0 * M_);
        const uint4* sb_hi = (const uint4*)(g_mhi + (size_t)n0 * M_);
        const uint4* sb_lo = (const uint4*)(g_mlo + (size_t)n0 * M_);
        #pragma unroll
        for (int it = 0; it < 4; ++it) {
            int idx = t + it * 256;                    // 1024 chunks each
            int r = idx >> 3, c = idx & 7;
            int off = r * RSTRIDE + c * 16;
            *(uint4*)(sm + OFF_A_HI + off) = sa_hi[idx];
            *(uint4*)(sm + OFF_A_LO + off) = sa_lo[idx];
            *(uint4*)(sm + OFF_B_HI + off) = sb_hi[idx];
            *(uint4*)(sm + OFF_B_LO + off) = sb_lo[idx];
        }
        if (t < 128) {
            ((float*)(sm + OFF_INV))[t] = g_inv_mn[n0 + t];
            ((float*)(sm + OFF_SBS))[t] = g_sb[b0 + t];
        }
    }
    __syncthreads();

    int wm = (wid >> 1) * 32;       // 0,32,64,96
    int wn = (wid & 1) * 64;        // 0,64
    int ltile = lane >> 3, lr = lane & 7;

    float acc[2][8][4];
    #pragma unroll
    for (int mi = 0; mi < 2; ++mi)
        #pragma unroll
        for (int nb = 0; nb < 8; ++nb)
            #pragma unroll
            for (int q = 0; q < 4; ++q) acc[mi][nb][q] = 0.f;

    #pragma unroll
    for (int pass = 0; pass < 3; ++pass) {
        uint32_t aOff = (pass == 2) ? OFF_A_LO : OFF_A_HI;
        uint32_t bOff = (pass == 1) ? OFF_B_LO : OFF_B_HI;
        #pragma unroll
        for (int ks = 0; ks < 4; ++ks) {
            uint32_t a[2][4];
            #pragma unroll
            for (int mi = 0; mi < 2; ++mi) {
                int rowA = wm + mi * 16 + (ltile & 1) * 8 + lr;
                int col16 = ks * 2 + (ltile >> 1);
                ldsm_x4(a[mi][0], a[mi][1], a[mi][2], a[mi][3],
                        sbase + aOff + rowA * RSTRIDE + col16 * 16);
            }
            uint32_t bfr[8][2];
            #pragma unroll
            for (int np = 0; np < 4; ++np) {
                int rowB = wn + np * 16 + (ltile >> 1) * 8 + lr;
                int col16 = ks * 2 + (ltile & 1);
                ldsm_x4(bfr[2 * np][0], bfr[2 * np][1], bfr[2 * np + 1][0], bfr[2 * np + 1][1],
                        sbase + bOff + rowB * RSTRIDE + col16 * 16);
            }
            #pragma unroll
            for (int mi = 0; mi < 2; ++mi)
                #pragma unroll
                for (int nb = 0; nb < 8; ++nb)
                    mma16816(acc[mi][nb], a[mi][0], a[mi][1], a[mi][2], a[mi][3],
                             bfr[nb][0], bfr[nb][1]);
        }
    }

    const float* inv_s = (const float*)(sm + OFF_INV);
    const float* sb_s  = (const float*)(sm + OFF_SBS);
    int r0 = lane >> 2, c0 = (lane & 3) * 2;
    #pragma unroll
    for (int mi = 0; mi < 2; ++mi) {
        int bl0 = wm + mi * 16 + r0;
        float s0 = sb_s[bl0], s1 = sb_s[bl0 + 8];
        float* d0 = &g_E[(size_t)(b0 + bl0) * N_ + n0];
        float* d1 = &g_E[(size_t)(b0 + bl0 + 8) * N_ + n0];
        #pragma unroll
        for (int nb = 0; nb < 8; ++nb) {
            int nl = wn + nb * 8 + c0;
            float i0 = inv_s[nl], i1 = inv_s[nl + 1];
            float2 e0, e1;
            e0.x = __expf(acc[mi][nb][0] * s0 * i0);
            e0.y = __expf(acc[mi][nb][1] * s0 * i1);
            e1.x = __expf(acc[mi][nb][2] * s1 * i0);
            e1.y = __expf(acc[mi][nb][3] * s1 * i1);
            *(float2*)(d0 + nl) = e0;
            *(float2*)(d1 + nl) = e1;
        }
    }
}

// ======================================================================
// Kernel 3: per-row fused tail (streaming, low-register).
// ======================================================================
__device__ __forceinline__ float blockReduceSum(float v, float* red) {
    int lane = threadIdx.x & 31, wid = threadIdx.x >> 5;
    #pragma unroll
    for (int o = 16; o; o >>= 1) v += __shfl_down_sync(0xffffffffu, v, o);
    if (lane == 0) red[wid] = v;
    __syncthreads();
    if (wid == 0) {
        float x = (lane < 16) ? red[lane] : 0.f;
        #pragma unroll
        for (int o = 8; o; o >>= 1) x += __shfl_down_sync(0xffffffffu, x, o);
        if (lane == 0) red[16] = x;
    }
    __syncthreads();
    return red[16];
}

__global__ void __launch_bounds__(512, 3) k_row(const float* __restrict__ w_tm1,
                                                float* __restrict__ out) {
    extern __shared__ float swg[];
    __shared__ float red[17];
    __shared__ float bnd[8];
    int t = threadIdx.x;
    int b = blockIdx.x;
    const float4* Erow = (const float4*)&g_E[(size_t)b * N_];
    const float4* Wrow = (const float4*)&w_tm1[(size_t)b * N_];
    float4* Orow = (float4*)&out[(size_t)b * N_];

    float se = 0.f;
    #pragma unroll
    for (int i = 0; i < 8; ++i) {
        int p = i * 512 + t;
        float4 e = Erow[p];
        *(float4*)&swg[p * 4] = e;
        se += e.x + e.y + e.z + e.w;
    }
    float inv_e = 1.0f / blockReduceSum(se, red);

    float g     = g_params[b * 8 + 2];
    float gamma = g_params[b * 8 + 3];
    float s0    = g_params[b * 8 + 4];
    float s1    = g_params[b * 8 + 5];
    float s2    = g_params[b * 8 + 6];
    float gs = g * inv_e, gi = 1.f - g;

    #pragma unroll
    for (int i = 0; i < 8; ++i) {
        int p = i * 512 + t;
        float4 e = *(float4*)&swg[p * 4];
        float4 wt = Wrow[p];
        float4 wg;
        wg.x = gs * e.x + gi * wt.x;
        wg.y = gs * e.y + gi * wt.y;
        wg.z = gs * e.z + gi * wt.z;
        wg.w = gs * e.w + gi * wt.w;
        *(float4*)&swg[p * 4] = wg;
    }
    __syncthreads();
    if (t < 8) bnd[t] = (t == 0) ? 0.f : swg[t * 2048 - 1];
    __syncthreads();

    float sw = 0.f;
    #pragma unroll
    for (int i = 0; i < 8; ++i) {
        int w0 = (i * 512 + t) * 4;
        float xm = (t == 0) ? bnd[i] : swg[w0 - 1];
        float4 x = *(float4*)&swg[w0];
        float xp = (w0 + 4 == N_) ? 0.f : swg[w0 + 4];
        float t0 = s0 * xm  + s1 * x.x + s2 * x.y;
        float t1 = s0 * x.x + s1 * x.y + s2 * x.z;
        float t2 = s0 * x.y + s1 * x.z + s2 * x.w;
        float t3 = s0 * x.z + s1 * x.w + s2 * xp;
        float p0 = __powf(t0 + 1e-6f, gamma);
        float p1 = __powf(t1 + 1e-6f, gamma);
        float p2 = __powf(t2 + 1e-6f, gamma);
        float p3 = __powf(t3 + 1e-6f, gamma);
        __syncthreads();
        *(float4*)&swg[w0] = make_float4(p0, p1, p2, p3);
        sw += p0 + p1 + p2 + p3;
    }
    float inv_w = 1.0f / blockReduceSum(sw, red);

    #pragma unroll
    for (int i = 0; i < 8; ++i) {
        int p = i * 512 + t;
        float4 x = *(float4*)&swg[p * 4];
        Orow[p] = make_float4(x.x * inv_w, x.y * inv_w, x.z * inv_w, x.w * inv_w);
    }
}

// ======================================================================
extern "C" void kernel_launch(void* const* d_in, const int* in_sizes, int n_in,
                              void* d_out, int out_size) {
    const float* h_t   = (const float*)d_in[0];
    const float* w_tm1 = (const float*)d_in[1];
    const float* m_t   = (const float*)d_in[2];
    const float* Wk    = (const float*)d_in[3];
    const float* bk    = (const float*)d_in[4];
    const float* Wb    = (const float*)d_in[5];
    const float* bb    = (const float*)d_in[6];
    const float* Wg    = (const float*)d_in[7];
    const float* bg    = (const float*)d_in[8];
    const float* Ws    = (const float*)d_in[9];
    const float* bs    = (const float*)d_in[10];
    const float* Wm    = (const float*)d_in[11];
    const float* bm    = (const float*)d_in[12];
    float* out = (float*)d_out;

    cudaFuncSetAttribute(k_gemm_hmma, cudaFuncAttributeMaxDynamicSharedMemorySize, SMEM_GEMM);
    cudaFuncSetAttribute(k_row,       cudaFuncAttributeMaxDynamicSharedMemorySize, 65536);

    k_prep<<<512, 256>>>(m_t, h_t, Wk, bk, Wb, bb, Wg, bg, Ws, bs, Wm, bm);
    k_gemm_hmma<<<dim3(N_ / 128, B_ / 128), 256, SMEM_GEMM>>>();
    k_row<<<B_, 512, 65536>>>(w_tm1, out);
}